// round 1
// baseline (speedup 1.0000x reference)
#include <cuda_runtime.h>
#include <math.h>

// ---------------- problem constants ----------------
#define NDIM      768
#define NTOK      512          // tokens per batch
#define BSZ       2
#define MALL      1024         // BSZ * NTOK
#define NHEADS    12
#define DHEAD     64
#define DMLP      3072
#define NDEPTH    4
#define QKVW      2304         // 3*NDIM
#define PATCHES   512          // 8*8*8 elements per patch

// ---------------- scratch (no runtime allocation allowed) ----------------
__device__ float g_patches[MALL * PATCHES];      // 2 MB  im2col
__device__ float g_wt[PATCHES * NDIM];           // 1.5MB conv_w transposed
__device__ float g_x[MALL * NDIM];               // residual stream
__device__ float g_h[MALL * NDIM];               // LN output
__device__ float g_qkv[MALL * QKVW];             // 9 MB
__device__ float g_scores[BSZ * NHEADS * NTOK * NTOK]; // 25 MB
__device__ float g_o[MALL * NDIM];               // attention output
__device__ float g_mlp[MALL * DMLP];             // 12 MB

// =====================================================================
// im2col: gather 8x8x8 patches from [B,1,64,64,64] volume
// out[(b*512+n)*512 + m], n=(pd*8+ph)*8+pw, m=i*64+j*8+k
// =====================================================================
__global__ void im2col_kernel(const float* __restrict__ vol, float* __restrict__ out)
{
    int idx = blockIdx.x * 256 + threadIdx.x;         // < 1024*512
    int m   = idx & 511;
    int tkn = idx >> 9;
    int n   = tkn & 511;
    int b   = tkn >> 9;
    int k = m & 7, j = (m >> 3) & 7, i = m >> 6;
    int pw = n & 7, ph = (n >> 3) & 7, pd = n >> 6;
    out[idx] = vol[((long)b << 18) + (pd * 8 + i) * 4096 + (ph * 8 + j) * 64 + (pw * 8 + k)];
}

// transpose conv_w [768,512] -> [512,768]
__global__ void transpose_w_kernel(const float* __restrict__ w, float* __restrict__ wt)
{
    int idx = blockIdx.x * 256 + threadIdx.x;   // < 768*512
    int k = idx / PATCHES;                      // out channel
    int j = idx % PATCHES;
    wt[j * NDIM + k] = w[idx];
}

// =====================================================================
// Generic tiled fp32 GEMM: C[M,K] = A[M,J] @ W[J,K]  (+ epilogue)
// BM=BN=64, BK=16, 256 threads, 4x4 per thread.
// All dims must be multiples of tile sizes (true for this problem).
// EPI: 0 store(+bias) | 1 residual C+=acc+bias | 2 tanh(acc+bias) | 3 acc+bias+pos
// =====================================================================
template <int EPI>
__global__ void gemm64_kernel(const float* __restrict__ A, const float* __restrict__ W,
                              float* __restrict__ C,
                              const float* __restrict__ bias,
                              const float* __restrict__ pos,
                              int J, int lda, int ldw, int ldc)
{
    __shared__ float As[16][68];
    __shared__ float Ws[16][68];

    const int tx = threadIdx.x, ty = threadIdx.y;
    const int tid  = ty * 16 + tx;
    const int row0 = blockIdx.y * 64;
    const int col0 = blockIdx.x * 64;

    const int arow = tid >> 2;          // 0..63
    const int acol = (tid & 3) * 4;     // 0..12
    const int wrow = tid >> 4;          // 0..15
    const int wcol = (tid & 15) * 4;    // 0..60

    float acc[4][4] = {};

    for (int j0 = 0; j0 < J; j0 += 16) {
        float4 av = *reinterpret_cast<const float4*>(&A[(long)(row0 + arow) * lda + j0 + acol]);
        float4 wv = *reinterpret_cast<const float4*>(&W[(long)(j0 + wrow) * ldw + col0 + wcol]);
        __syncthreads();
        As[acol + 0][arow] = av.x;
        As[acol + 1][arow] = av.y;
        As[acol + 2][arow] = av.z;
        As[acol + 3][arow] = av.w;
        *reinterpret_cast<float4*>(&Ws[wrow][wcol]) = wv;
        __syncthreads();
#pragma unroll
        for (int kk = 0; kk < 16; ++kk) {
            float4 a = *reinterpret_cast<const float4*>(&As[kk][ty * 4]);
            float4 b = *reinterpret_cast<const float4*>(&Ws[kk][tx * 4]);
            float ar[4] = {a.x, a.y, a.z, a.w};
            float br[4] = {b.x, b.y, b.z, b.w};
#pragma unroll
            for (int r = 0; r < 4; ++r)
#pragma unroll
                for (int c = 0; c < 4; ++c)
                    acc[r][c] += ar[r] * br[c];
        }
    }

    const int gc = col0 + tx * 4;
#pragma unroll
    for (int r = 0; r < 4; ++r) {
        int grow = row0 + ty * 4 + r;
        float* cp = &C[(long)grow * ldc + gc];
        float v[4];
#pragma unroll
        for (int c = 0; c < 4; ++c) {
            v[c] = acc[r][c];
            if (bias) v[c] += bias[gc + c];
        }
        if (EPI == 1) {
            float4 cur = *reinterpret_cast<const float4*>(cp);
            v[0] += cur.x; v[1] += cur.y; v[2] += cur.z; v[3] += cur.w;
        } else if (EPI == 2) {
#pragma unroll
            for (int c = 0; c < 4; ++c) v[c] = tanhf(v[c]);
        } else if (EPI == 3) {
            const float* pp = &pos[(long)(grow & (NTOK - 1)) * ldc + gc];
            float4 pv = *reinterpret_cast<const float4*>(pp);
            v[0] += pv.x; v[1] += pv.y; v[2] += pv.z; v[3] += pv.w;
        }
        *reinterpret_cast<float4*>(cp) = make_float4(v[0], v[1], v[2], v[3]);
    }
}

// =====================================================================
// S[bh] = scale * Q[bh] @ K[bh]^T   (Q,K rows inside qkv, stride 2304)
// grid: (8 jtile, 8 itile, 24 bh), block 16x16
// =====================================================================
__global__ void qk_kernel(const float* __restrict__ qkv, float* __restrict__ scores)
{
    __shared__ float Qs[16][68];
    __shared__ float Ks[16][68];

    const int z = blockIdx.z;
    const int b = z / NHEADS, h = z % NHEADS;
    const float* Q  = qkv + (long)b * NTOK * QKVW + h * DHEAD;
    const float* Kp = Q + NDIM;
    float* S = scores + (long)z * NTOK * NTOK;

    const int i0 = blockIdx.y * 64, j0 = blockIdx.x * 64;
    const int tx = threadIdx.x, ty = threadIdx.y;
    const int tid  = ty * 16 + tx;
    const int arow = tid >> 2;
    const int acol = (tid & 3) * 4;

    float acc[4][4] = {};

    for (int d0 = 0; d0 < DHEAD; d0 += 16) {
        float4 qv = *reinterpret_cast<const float4*>(&Q [(long)(i0 + arow) * QKVW + d0 + acol]);
        float4 kv = *reinterpret_cast<const float4*>(&Kp[(long)(j0 + arow) * QKVW + d0 + acol]);
        __syncthreads();
        Qs[acol + 0][arow] = qv.x; Qs[acol + 1][arow] = qv.y;
        Qs[acol + 2][arow] = qv.z; Qs[acol + 3][arow] = qv.w;
        Ks[acol + 0][arow] = kv.x; Ks[acol + 1][arow] = kv.y;
        Ks[acol + 2][arow] = kv.z; Ks[acol + 3][arow] = kv.w;
        __syncthreads();
#pragma unroll
        for (int kk = 0; kk < 16; ++kk) {
            float4 a = *reinterpret_cast<const float4*>(&Qs[kk][ty * 4]);
            float4 b4 = *reinterpret_cast<const float4*>(&Ks[kk][tx * 4]);
            float ar[4] = {a.x, a.y, a.z, a.w};
            float br[4] = {b4.x, b4.y, b4.z, b4.w};
#pragma unroll
            for (int r = 0; r < 4; ++r)
#pragma unroll
                for (int c = 0; c < 4; ++c)
                    acc[r][c] += ar[r] * br[c];
        }
    }

    const float scale = 0.125f;   // 64^-0.5
#pragma unroll
    for (int r = 0; r < 4; ++r) {
        float* sp = &S[(long)(i0 + ty * 4 + r) * NTOK + j0 + tx * 4];
        *reinterpret_cast<float4*>(sp) =
            make_float4(acc[r][0] * scale, acc[r][1] * scale, acc[r][2] * scale, acc[r][3] * scale);
    }
}

// =====================================================================
// row softmax over 512 columns, one block (128 thr) per row, in-place
// =====================================================================
__global__ void softmax_kernel(float* __restrict__ sc)
{
    __shared__ float redm[4];
    __shared__ float reds[4];
    float* p = sc + (long)blockIdx.x * NTOK;
    const int t = threadIdx.x;
    float4 v = *reinterpret_cast<float4*>(&p[t * 4]);

    float m = fmaxf(fmaxf(v.x, v.y), fmaxf(v.z, v.w));
#pragma unroll
    for (int o = 16; o; o >>= 1) m = fmaxf(m, __shfl_xor_sync(0xffffffffu, m, o));
    if ((t & 31) == 0) redm[t >> 5] = m;
    __syncthreads();
    m = fmaxf(fmaxf(redm[0], redm[1]), fmaxf(redm[2], redm[3]));

    v.x = __expf(v.x - m); v.y = __expf(v.y - m);
    v.z = __expf(v.z - m); v.w = __expf(v.w - m);
    float s = v.x + v.y + v.z + v.w;
#pragma unroll
    for (int o = 16; o; o >>= 1) s += __shfl_xor_sync(0xffffffffu, s, o);
    if ((t & 31) == 0) reds[t >> 5] = s;
    __syncthreads();
    s = reds[0] + reds[1] + reds[2] + reds[3];

    float inv = 1.0f / s;
    v.x *= inv; v.y *= inv; v.z *= inv; v.w *= inv;
    *reinterpret_cast<float4*>(&p[t * 4]) = v;
}

// =====================================================================
// O[bh] = P[bh] @ V[bh]   P:[512,512], V:[512,64] (stride 2304)
// grid: (1, 8 row tiles, 24 bh)
// =====================================================================
__global__ void pv_kernel(const float* __restrict__ scores, const float* __restrict__ qkv,
                          float* __restrict__ o)
{
    __shared__ float As[16][68];
    __shared__ float Vs[16][68];

    const int z = blockIdx.z;
    const int b = z / NHEADS, h = z % NHEADS;
    const float* A = scores + (long)z * NTOK * NTOK;
    const float* V = qkv + (long)b * NTOK * QKVW + 2 * NDIM + h * DHEAD;
    float* C = o + (long)b * NTOK * NDIM + h * DHEAD;

    const int row0 = blockIdx.y * 64;
    const int tx = threadIdx.x, ty = threadIdx.y;
    const int tid  = ty * 16 + tx;
    const int arow = tid >> 2;
    const int acol = (tid & 3) * 4;
    const int wrow = tid >> 4;
    const int wcol = (tid & 15) * 4;

    float acc[4][4] = {};

    for (int j0 = 0; j0 < NTOK; j0 += 16) {
        float4 av = *reinterpret_cast<const float4*>(&A[(long)(row0 + arow) * NTOK + j0 + acol]);
        float4 wv = *reinterpret_cast<const float4*>(&V[(long)(j0 + wrow) * QKVW + wcol]);
        __syncthreads();
        As[acol + 0][arow] = av.x; As[acol + 1][arow] = av.y;
        As[acol + 2][arow] = av.z; As[acol + 3][arow] = av.w;
        *reinterpret_cast<float4*>(&Vs[wrow][wcol]) = wv;
        __syncthreads();
#pragma unroll
        for (int kk = 0; kk < 16; ++kk) {
            float4 a  = *reinterpret_cast<const float4*>(&As[kk][ty * 4]);
            float4 b4 = *reinterpret_cast<const float4*>(&Vs[kk][tx * 4]);
            float ar[4] = {a.x, a.y, a.z, a.w};
            float br[4] = {b4.x, b4.y, b4.z, b4.w};
#pragma unroll
            for (int r = 0; r < 4; ++r)
#pragma unroll
                for (int c = 0; c < 4; ++c)
                    acc[r][c] += ar[r] * br[c];
        }
    }
#pragma unroll
    for (int r = 0; r < 4; ++r) {
        float* cp = &C[(long)(row0 + ty * 4 + r) * NDIM + tx * 4];
        *reinterpret_cast<float4*>(cp) = make_float4(acc[r][0], acc[r][1], acc[r][2], acc[r][3]);
    }
}

// =====================================================================
// LayerNorm over last dim (768), one block (256 thr) per row
// =====================================================================
__global__ void ln_kernel(const float* __restrict__ x, const float* __restrict__ w,
                          const float* __restrict__ bb, float* __restrict__ out)
{
    __shared__ float red[8];
    const int row = blockIdx.x;
    const float* xp = x + (long)row * NDIM;
    const int t = threadIdx.x;

    float v0 = xp[t], v1 = xp[t + 256], v2 = xp[t + 512];

    float s = v0 + v1 + v2;
#pragma unroll
    for (int o = 16; o; o >>= 1) s += __shfl_xor_sync(0xffffffffu, s, o);
    if ((t & 31) == 0) red[t >> 5] = s;
    __syncthreads();
    if (t < 32) {
        float r = (t < 8) ? red[t] : 0.0f;
#pragma unroll
        for (int o = 4; o; o >>= 1) r += __shfl_xor_sync(0xffffffffu, r, o);
        if (t == 0) red[0] = r;
    }
    __syncthreads();
    float mean = red[0] * (1.0f / NDIM);
    __syncthreads();

    float d0 = v0 - mean, d1 = v1 - mean, d2 = v2 - mean;
    float q = d0 * d0 + d1 * d1 + d2 * d2;
#pragma unroll
    for (int o = 16; o; o >>= 1) q += __shfl_xor_sync(0xffffffffu, q, o);
    if ((t & 31) == 0) red[t >> 5] = q;
    __syncthreads();
    if (t < 32) {
        float r = (t < 8) ? red[t] : 0.0f;
#pragma unroll
        for (int o = 4; o; o >>= 1) r += __shfl_xor_sync(0xffffffffu, r, o);
        if (t == 0) red[0] = r;
    }
    __syncthreads();
    float rs = rsqrtf(red[0] * (1.0f / NDIM) + 1e-5f);

    float* op = out + (long)row * NDIM;
    op[t]       = d0 * rs * w[t]       + bb[t];
    op[t + 256] = d1 * rs * w[t + 256] + bb[t + 256];
    op[t + 512] = d2 * rs * w[t + 512] + bb[t + 512];
}

// =====================================================================
// host side
// =====================================================================
extern "C" void kernel_launch(void* const* d_in, const int* in_sizes, int n_in,
                              void* d_out, int out_size)
{
    const float* volume    = (const float*)d_in[0];
    const float* conv_w    = (const float*)d_in[1];
    const float* conv_b    = (const float*)d_in[2];
    const float* pos_embed = (const float*)d_in[3];
    const float* ln1_w     = (const float*)d_in[4];
    const float* ln1_b     = (const float*)d_in[5];
    const float* w_qkv     = (const float*)d_in[6];
    const float* w_o       = (const float*)d_in[7];
    const float* b_o       = (const float*)d_in[8];
    const float* ln2_w     = (const float*)d_in[9];
    const float* ln2_b     = (const float*)d_in[10];
    const float* w1        = (const float*)d_in[11];
    const float* b1        = (const float*)d_in[12];
    const float* w2        = (const float*)d_in[13];
    const float* b2        = (const float*)d_in[14];
    const float* lnf_w     = (const float*)d_in[15];
    const float* lnf_b     = (const float*)d_in[16];
    float* out = (float*)d_out;

    float *patches, *wt, *x, *h, *qkv, *scores, *o, *mlp;
    cudaGetSymbolAddress((void**)&patches, g_patches);
    cudaGetSymbolAddress((void**)&wt,      g_wt);
    cudaGetSymbolAddress((void**)&x,       g_x);
    cudaGetSymbolAddress((void**)&h,       g_h);
    cudaGetSymbolAddress((void**)&qkv,     g_qkv);
    cudaGetSymbolAddress((void**)&scores,  g_scores);
    cudaGetSymbolAddress((void**)&o,       g_o);
    cudaGetSymbolAddress((void**)&mlp,     g_mlp);

    dim3 blk(16, 16);

    // patch embedding
    im2col_kernel<<<(MALL * PATCHES) / 256, 256>>>(volume, patches);
    transpose_w_kernel<<<(NDIM * PATCHES) / 256, 256>>>(conv_w, wt);
    // x = patches @ wt + conv_b + pos_embed
    gemm64_kernel<3><<<dim3(NDIM / 64, MALL / 64), blk>>>(
        patches, wt, x, conv_b, pos_embed, PATCHES, PATCHES, NDIM, NDIM);

    for (int l = 0; l < NDEPTH; ++l) {
        const float* Wqkv = w_qkv + (long)l * NDIM * QKVW;
        const float* Wo   = w_o   + (long)l * NDIM * NDIM;
        const float* Bo   = b_o   + (long)l * NDIM;
        const float* W1   = w1    + (long)l * NDIM * DMLP;
        const float* B1   = b1    + (long)l * DMLP;
        const float* W2   = w2    + (long)l * DMLP * NDIM;
        const float* B2   = b2    + (long)l * NDIM;

        // h = LN1(x)
        ln_kernel<<<MALL, 256>>>(x, ln1_w + l * NDIM, ln1_b + l * NDIM, h);
        // qkv = h @ Wqkv
        gemm64_kernel<0><<<dim3(QKVW / 64, MALL / 64), blk>>>(
            h, Wqkv, qkv, nullptr, nullptr, NDIM, NDIM, QKVW, QKVW);
        // S = scale * Q K^T
        qk_kernel<<<dim3(NTOK / 64, NTOK / 64, BSZ * NHEADS), blk>>>(qkv, scores);
        // softmax rows
        softmax_kernel<<<BSZ * NHEADS * NTOK, 128>>>(scores);
        // o = P V
        pv_kernel<<<dim3(1, NTOK / 64, BSZ * NHEADS), blk>>>(scores, qkv, o);
        // x += o @ Wo + Bo
        gemm64_kernel<1><<<dim3(NDIM / 64, MALL / 64), blk>>>(
            o, Wo, x, Bo, nullptr, NDIM, NDIM, NDIM, NDIM);
        // h = LN2(x)
        ln_kernel<<<MALL, 256>>>(x, ln2_w + l * NDIM, ln2_b + l * NDIM, h);
        // mlp = tanh(h @ W1 + B1)
        gemm64_kernel<2><<<dim3(DMLP / 64, MALL / 64), blk>>>(
            h, W1, mlp, B1, nullptr, NDIM, NDIM, DMLP, DMLP);
        // x += mlp @ W2 + B2
        gemm64_kernel<1><<<dim3(NDIM / 64, MALL / 64), blk>>>(
            mlp, W2, x, B2, nullptr, DMLP, DMLP, NDIM, NDIM);
    }

    // out = LN_f(x)
    ln_kernel<<<MALL, 256>>>(x, lnf_w, lnf_b, out);
}

// round 2
// speedup vs baseline: 1.0017x; 1.0017x over previous
#include <cuda_runtime.h>
#include <math.h>

// ---------------- problem constants ----------------
#define NDIM      768
#define NTOK      512          // tokens per batch
#define BSZ       2
#define MALL      1024         // BSZ * NTOK
#define NHEADS    12
#define DHEAD     64
#define DMLP      3072
#define NDEPTH    4
#define QKVW      2304         // 3*NDIM
#define PATCHES   512          // 8*8*8 elements per patch

// ---------------- scratch (no runtime allocation allowed) ----------------
__device__ float g_patches[MALL * PATCHES];      // 2 MB  im2col
__device__ float g_wt[PATCHES * NDIM];           // 1.5MB conv_w transposed
__device__ float g_x[MALL * NDIM];               // residual stream
__device__ float g_h[MALL * NDIM];               // LN output
__device__ float g_qkv[MALL * QKVW];             // 9 MB
__device__ float g_scores[BSZ * NHEADS * NTOK * NTOK]; // 25 MB
__device__ float g_o[MALL * NDIM];               // attention output
__device__ float g_mlp[MALL * DMLP];             // 12 MB

// =====================================================================
// im2col: gather 8x8x8 patches from [B,1,64,64,64] volume
// out[(b*512+n)*512 + m], n=(pd*8+ph)*8+pw, m=i*64+j*8+k
// =====================================================================
__global__ void im2col_kernel(const float* __restrict__ vol, float* __restrict__ out)
{
    int idx = blockIdx.x * 256 + threadIdx.x;         // < 1024*512
    int m   = idx & 511;
    int tkn = idx >> 9;
    int n   = tkn & 511;
    int b   = tkn >> 9;
    int k = m & 7, j = (m >> 3) & 7, i = m >> 6;
    int pw = n & 7, ph = (n >> 3) & 7, pd = n >> 6;
    out[idx] = vol[((long)b << 18) + (pd * 8 + i) * 4096 + (ph * 8 + j) * 64 + (pw * 8 + k)];
}

// transpose conv_w [768,512] -> [512,768]
__global__ void transpose_w_kernel(const float* __restrict__ w, float* __restrict__ wt)
{
    int idx = blockIdx.x * 256 + threadIdx.x;   // < 768*512
    int k = idx / PATCHES;                      // out channel
    int j = idx % PATCHES;
    wt[j * NDIM + k] = w[idx];
}

// =====================================================================
// Generic tiled fp32 GEMM: C[M,K] = A[M,J] @ W[J,K]  (+ epilogue)
// BM=BN=64, BK=16, 256 threads, 4x4 per thread.
// All dims must be multiples of tile sizes (true for this problem).
// EPI: 0 store(+bias) | 1 residual C+=acc+bias | 2 tanh(acc+bias) | 3 acc+bias+pos
// =====================================================================
template <int EPI>
__global__ void gemm64_kernel(const float* __restrict__ A, const float* __restrict__ W,
                              float* __restrict__ C,
                              const float* __restrict__ bias,
                              const float* __restrict__ pos,
                              int J, int lda, int ldw, int ldc)
{
    __shared__ float As[16][68];
    __shared__ float Ws[16][68];

    const int tx = threadIdx.x, ty = threadIdx.y;
    const int tid  = ty * 16 + tx;
    const int row0 = blockIdx.y * 64;
    const int col0 = blockIdx.x * 64;

    const int arow = tid >> 2;          // 0..63
    const int acol = (tid & 3) * 4;     // 0..12
    const int wrow = tid >> 4;          // 0..15
    const int wcol = (tid & 15) * 4;    // 0..60

    float acc[4][4] = {};

    for (int j0 = 0; j0 < J; j0 += 16) {
        float4 av = *reinterpret_cast<const float4*>(&A[(long)(row0 + arow) * lda + j0 + acol]);
        float4 wv = *reinterpret_cast<const float4*>(&W[(long)(j0 + wrow) * ldw + col0 + wcol]);
        __syncthreads();
        As[acol + 0][arow] = av.x;
        As[acol + 1][arow] = av.y;
        As[acol + 2][arow] = av.z;
        As[acol + 3][arow] = av.w;
        *reinterpret_cast<float4*>(&Ws[wrow][wcol]) = wv;
        __syncthreads();
#pragma unroll
        for (int kk = 0; kk < 16; ++kk) {
            float4 a = *reinterpret_cast<const float4*>(&As[kk][ty * 4]);
            float4 b = *reinterpret_cast<const float4*>(&Ws[kk][tx * 4]);
            float ar[4] = {a.x, a.y, a.z, a.w};
            float br[4] = {b.x, b.y, b.z, b.w};
#pragma unroll
            for (int r = 0; r < 4; ++r)
#pragma unroll
                for (int c = 0; c < 4; ++c)
                    acc[r][c] += ar[r] * br[c];
        }
    }

    const int gc = col0 + tx * 4;
#pragma unroll
    for (int r = 0; r < 4; ++r) {
        int grow = row0 + ty * 4 + r;
        float* cp = &C[(long)grow * ldc + gc];
        float v[4];
#pragma unroll
        for (int c = 0; c < 4; ++c) {
            v[c] = acc[r][c];
            if (bias) v[c] += bias[gc + c];
        }
        if (EPI == 1) {
            float4 cur = *reinterpret_cast<const float4*>(cp);
            v[0] += cur.x; v[1] += cur.y; v[2] += cur.z; v[3] += cur.w;
        } else if (EPI == 2) {
#pragma unroll
            for (int c = 0; c < 4; ++c) v[c] = tanhf(v[c]);
        } else if (EPI == 3) {
            const float* pp = &pos[(long)(grow & (NTOK - 1)) * ldc + gc];
            float4 pv = *reinterpret_cast<const float4*>(pp);
            v[0] += pv.x; v[1] += pv.y; v[2] += pv.z; v[3] += pv.w;
        }
        *reinterpret_cast<float4*>(cp) = make_float4(v[0], v[1], v[2], v[3]);
    }
}

// =====================================================================
// S[bh] = scale * Q[bh] @ K[bh]^T   (Q,K rows inside qkv, stride 2304)
// grid: (8 jtile, 8 itile, 24 bh), block 16x16
// =====================================================================
__global__ void qk_kernel(const float* __restrict__ qkv, float* __restrict__ scores)
{
    __shared__ float Qs[16][68];
    __shared__ float Ks[16][68];

    const int z = blockIdx.z;
    const int b = z / NHEADS, h = z % NHEADS;
    const float* Q  = qkv + (long)b * NTOK * QKVW + h * DHEAD;
    const float* Kp = Q + NDIM;
    float* S = scores + (long)z * NTOK * NTOK;

    const int i0 = blockIdx.y * 64, j0 = blockIdx.x * 64;
    const int tx = threadIdx.x, ty = threadIdx.y;
    const int tid  = ty * 16 + tx;
    const int arow = tid >> 2;
    const int acol = (tid & 3) * 4;

    float acc[4][4] = {};

    for (int d0 = 0; d0 < DHEAD; d0 += 16) {
        float4 qv = *reinterpret_cast<const float4*>(&Q [(long)(i0 + arow) * QKVW + d0 + acol]);
        float4 kv = *reinterpret_cast<const float4*>(&Kp[(long)(j0 + arow) * QKVW + d0 + acol]);
        __syncthreads();
        Qs[acol + 0][arow] = qv.x; Qs[acol + 1][arow] = qv.y;
        Qs[acol + 2][arow] = qv.z; Qs[acol + 3][arow] = qv.w;
        Ks[acol + 0][arow] = kv.x; Ks[acol + 1][arow] = kv.y;
        Ks[acol + 2][arow] = kv.z; Ks[acol + 3][arow] = kv.w;
        __syncthreads();
#pragma unroll
        for (int kk = 0; kk < 16; ++kk) {
            float4 a = *reinterpret_cast<const float4*>(&Qs[kk][ty * 4]);
            float4 b4 = *reinterpret_cast<const float4*>(&Ks[kk][tx * 4]);
            float ar[4] = {a.x, a.y, a.z, a.w};
            float br[4] = {b4.x, b4.y, b4.z, b4.w};
#pragma unroll
            for (int r = 0; r < 4; ++r)
#pragma unroll
                for (int c = 0; c < 4; ++c)
                    acc[r][c] += ar[r] * br[c];
        }
    }

    const float scale = 0.125f;   // 64^-0.5
#pragma unroll
    for (int r = 0; r < 4; ++r) {
        float* sp = &S[(long)(i0 + ty * 4 + r) * NTOK + j0 + tx * 4];
        *reinterpret_cast<float4*>(sp) =
            make_float4(acc[r][0] * scale, acc[r][1] * scale, acc[r][2] * scale, acc[r][3] * scale);
    }
}

// =====================================================================
// row softmax over 512 columns, one block (128 thr) per row, in-place
// =====================================================================
__global__ void softmax_kernel(float* __restrict__ sc)
{
    __shared__ float redm[4];
    __shared__ float reds[4];
    float* p = sc + (long)blockIdx.x * NTOK;
    const int t = threadIdx.x;
    float4 v = *reinterpret_cast<float4*>(&p[t * 4]);

    float m = fmaxf(fmaxf(v.x, v.y), fmaxf(v.z, v.w));
#pragma unroll
    for (int o = 16; o; o >>= 1) m = fmaxf(m, __shfl_xor_sync(0xffffffffu, m, o));
    if ((t & 31) == 0) redm[t >> 5] = m;
    __syncthreads();
    m = fmaxf(fmaxf(redm[0], redm[1]), fmaxf(redm[2], redm[3]));

    v.x = __expf(v.x - m); v.y = __expf(v.y - m);
    v.z = __expf(v.z - m); v.w = __expf(v.w - m);
    float s = v.x + v.y + v.z + v.w;
#pragma unroll
    for (int o = 16; o; o >>= 1) s += __shfl_xor_sync(0xffffffffu, s, o);
    if ((t & 31) == 0) reds[t >> 5] = s;
    __syncthreads();
    s = reds[0] + reds[1] + reds[2] + reds[3];

    float inv = 1.0f / s;
    v.x *= inv; v.y *= inv; v.z *= inv; v.w *= inv;
    *reinterpret_cast<float4*>(&p[t * 4]) = v;
}

// =====================================================================
// O[bh] = P[bh] @ V[bh]   P:[512,512], V:[512,64] (stride 2304)
// grid: (1, 8 row tiles, 24 bh)
// =====================================================================
__global__ void pv_kernel(const float* __restrict__ scores, const float* __restrict__ qkv,
                          float* __restrict__ o)
{
    __shared__ float As[16][68];
    __shared__ float Vs[16][68];

    const int z = blockIdx.z;
    const int b = z / NHEADS, h = z % NHEADS;
    const float* A = scores + (long)z * NTOK * NTOK;
    const float* V = qkv + (long)b * NTOK * QKVW + 2 * NDIM + h * DHEAD;
    float* C = o + (long)b * NTOK * NDIM + h * DHEAD;

    const int row0 = blockIdx.y * 64;
    const int tx = threadIdx.x, ty = threadIdx.y;
    const int tid  = ty * 16 + tx;
    const int arow = tid >> 2;
    const int acol = (tid & 3) * 4;
    const int wrow = tid >> 4;
    const int wcol = (tid & 15) * 4;

    float acc[4][4] = {};

    for (int j0 = 0; j0 < NTOK; j0 += 16) {
        float4 av = *reinterpret_cast<const float4*>(&A[(long)(row0 + arow) * NTOK + j0 + acol]);
        float4 wv = *reinterpret_cast<const float4*>(&V[(long)(j0 + wrow) * QKVW + wcol]);
        __syncthreads();
        As[acol + 0][arow] = av.x; As[acol + 1][arow] = av.y;
        As[acol + 2][arow] = av.z; As[acol + 3][arow] = av.w;
        *reinterpret_cast<float4*>(&Vs[wrow][wcol]) = wv;
        __syncthreads();
#pragma unroll
        for (int kk = 0; kk < 16; ++kk) {
            float4 a  = *reinterpret_cast<const float4*>(&As[kk][ty * 4]);
            float4 b4 = *reinterpret_cast<const float4*>(&Vs[kk][tx * 4]);
            float ar[4] = {a.x, a.y, a.z, a.w};
            float br[4] = {b4.x, b4.y, b4.z, b4.w};
#pragma unroll
            for (int r = 0; r < 4; ++r)
#pragma unroll
                for (int c = 0; c < 4; ++c)
                    acc[r][c] += ar[r] * br[c];
        }
    }
#pragma unroll
    for (int r = 0; r < 4; ++r) {
        float* cp = &C[(long)(row0 + ty * 4 + r) * NDIM + tx * 4];
        *reinterpret_cast<float4*>(cp) = make_float4(acc[r][0], acc[r][1], acc[r][2], acc[r][3]);
    }
}

// =====================================================================
// LayerNorm over last dim (768), one block (256 thr) per row
// =====================================================================
__global__ void ln_kernel(const float* __restrict__ x, const float* __restrict__ w,
                          const float* __restrict__ bb, float* __restrict__ out)
{
    __shared__ float red[8];
    const int row = blockIdx.x;
    const float* xp = x + (long)row * NDIM;
    const int t = threadIdx.x;

    float v0 = xp[t], v1 = xp[t + 256], v2 = xp[t + 512];

    float s = v0 + v1 + v2;
#pragma unroll
    for (int o = 16; o; o >>= 1) s += __shfl_xor_sync(0xffffffffu, s, o);
    if ((t & 31) == 0) red[t >> 5] = s;
    __syncthreads();
    if (t < 32) {
        float r = (t < 8) ? red[t] : 0.0f;
#pragma unroll
        for (int o = 4; o; o >>= 1) r += __shfl_xor_sync(0xffffffffu, r, o);
        if (t == 0) red[0] = r;
    }
    __syncthreads();
    float mean = red[0] * (1.0f / NDIM);
    __syncthreads();

    float d0 = v0 - mean, d1 = v1 - mean, d2 = v2 - mean;
    float q = d0 * d0 + d1 * d1 + d2 * d2;
#pragma unroll
    for (int o = 16; o; o >>= 1) q += __shfl_xor_sync(0xffffffffu, q, o);
    if ((t & 31) == 0) red[t >> 5] = q;
    __syncthreads();
    if (t < 32) {
        float r = (t < 8) ? red[t] : 0.0f;
#pragma unroll
        for (int o = 4; o; o >>= 1) r += __shfl_xor_sync(0xffffffffu, r, o);
        if (t == 0) red[0] = r;
    }
    __syncthreads();
    float rs = rsqrtf(red[0] * (1.0f / NDIM) + 1e-5f);

    float* op = out + (long)row * NDIM;
    op[t]       = d0 * rs * w[t]       + bb[t];
    op[t + 256] = d1 * rs * w[t + 256] + bb[t + 256];
    op[t + 512] = d2 * rs * w[t + 512] + bb[t + 512];
}

// =====================================================================
// host side
// =====================================================================
extern "C" void kernel_launch(void* const* d_in, const int* in_sizes, int n_in,
                              void* d_out, int out_size)
{
    const float* volume    = (const float*)d_in[0];
    const float* conv_w    = (const float*)d_in[1];
    const float* conv_b    = (const float*)d_in[2];
    const float* pos_embed = (const float*)d_in[3];
    const float* ln1_w     = (const float*)d_in[4];
    const float* ln1_b     = (const float*)d_in[5];
    const float* w_qkv     = (const float*)d_in[6];
    const float* w_o       = (const float*)d_in[7];
    const float* b_o       = (const float*)d_in[8];
    const float* ln2_w     = (const float*)d_in[9];
    const float* ln2_b     = (const float*)d_in[10];
    const float* w1        = (const float*)d_in[11];
    const float* b1        = (const float*)d_in[12];
    const float* w2        = (const float*)d_in[13];
    const float* b2        = (const float*)d_in[14];
    const float* lnf_w     = (const float*)d_in[15];
    const float* lnf_b     = (const float*)d_in[16];
    float* out = (float*)d_out;

    float *patches, *wt, *x, *h, *qkv, *scores, *o, *mlp;
    cudaGetSymbolAddress((void**)&patches, g_patches);
    cudaGetSymbolAddress((void**)&wt,      g_wt);
    cudaGetSymbolAddress((void**)&x,       g_x);
    cudaGetSymbolAddress((void**)&h,       g_h);
    cudaGetSymbolAddress((void**)&qkv,     g_qkv);
    cudaGetSymbolAddress((void**)&scores,  g_scores);
    cudaGetSymbolAddress((void**)&o,       g_o);
    cudaGetSymbolAddress((void**)&mlp,     g_mlp);

    dim3 blk(16, 16);

    // patch embedding
    im2col_kernel<<<(MALL * PATCHES) / 256, 256>>>(volume, patches);
    transpose_w_kernel<<<(NDIM * PATCHES) / 256, 256>>>(conv_w, wt);
    // x = patches @ wt + conv_b + pos_embed
    gemm64_kernel<3><<<dim3(NDIM / 64, MALL / 64), blk>>>(
        patches, wt, x, conv_b, pos_embed, PATCHES, PATCHES, NDIM, NDIM);

    for (int l = 0; l < NDEPTH; ++l) {
        const float* Wqkv = w_qkv + (long)l * NDIM * QKVW;
        const float* Wo   = w_o   + (long)l * NDIM * NDIM;
        const float* Bo   = b_o   + (long)l * NDIM;
        const float* W1   = w1    + (long)l * NDIM * DMLP;
        const float* B1   = b1    + (long)l * DMLP;
        const float* W2   = w2    + (long)l * DMLP * NDIM;
        const float* B2   = b2    + (long)l * NDIM;

        // h = LN1(x)
        ln_kernel<<<MALL, 256>>>(x, ln1_w + l * NDIM, ln1_b + l * NDIM, h);
        // qkv = h @ Wqkv
        gemm64_kernel<0><<<dim3(QKVW / 64, MALL / 64), blk>>>(
            h, Wqkv, qkv, nullptr, nullptr, NDIM, NDIM, QKVW, QKVW);
        // S = scale * Q K^T
        qk_kernel<<<dim3(NTOK / 64, NTOK / 64, BSZ * NHEADS), blk>>>(qkv, scores);
        // softmax rows
        softmax_kernel<<<BSZ * NHEADS * NTOK, 128>>>(scores);
        // o = P V
        pv_kernel<<<dim3(1, NTOK / 64, BSZ * NHEADS), blk>>>(scores, qkv, o);
        // x += o @ Wo + Bo
        gemm64_kernel<1><<<dim3(NDIM / 64, MALL / 64), blk>>>(
            o, Wo, x, Bo, nullptr, NDIM, NDIM, NDIM, NDIM);
        // h = LN2(x)
        ln_kernel<<<MALL, 256>>>(x, ln2_w + l * NDIM, ln2_b + l * NDIM, h);
        // mlp = tanh(h @ W1 + B1)
        gemm64_kernel<2><<<dim3(DMLP / 64, MALL / 64), blk>>>(
            h, W1, mlp, B1, nullptr, NDIM, NDIM, DMLP, DMLP);
        // x += mlp @ W2 + B2
        gemm64_kernel<1><<<dim3(NDIM / 64, MALL / 64), blk>>>(
            mlp, W2, x, B2, nullptr, DMLP, DMLP, NDIM, NDIM);
    }

    // out = LN_f(x)
    ln_kernel<<<MALL, 256>>>(x, lnf_w, lnf_b, out);
}

// round 4
// speedup vs baseline: 1.6315x; 1.6287x over previous
#include <cuda_runtime.h>
#include <cuda_bf16.h>
#include <cstdint>
#include <math.h>

#define NDIM 768
#define NTOK 512
#define BSZ 2
#define MALL 1024
#define NHEADS 12
#define DHEAD 64
#define DMLP 3072
#define NDEPTH 4
#define QKVW 2304
#define PATCHES 512
#define NBH (BSZ*NHEADS)

__device__ __forceinline__ uint32_t smem_u32(const void* p){
    uint32_t a;
    asm("{ .reg .u64 t; cvta.to.shared.u64 t, %1; cvt.u32.u64 %0, t; }" : "=r"(a) : "l"(p));
    return a;
}
#define CPA16(d, s) asm volatile("cp.async.cg.shared.global [%0], [%1], 16;" :: "r"(d), "l"(s))
#define CP_COMMIT() asm volatile("cp.async.commit_group;" ::: "memory")
#define CP_WAIT1()  asm volatile("cp.async.wait_group 1;" ::: "memory")
#define CP_WAIT0()  asm volatile("cp.async.wait_group 0;" ::: "memory")

__device__ __forceinline__ void ldm4(uint32_t addr, uint32_t* r){
    asm volatile("ldmatrix.sync.aligned.m8n8.x4.shared.b16 {%0,%1,%2,%3}, [%4];"
        : "=r"(r[0]), "=r"(r[1]), "=r"(r[2]), "=r"(r[3]) : "r"(addr));
}
__device__ __forceinline__ void mma16816(float* c, const uint32_t* a, const uint32_t* b){
    asm volatile("mma.sync.aligned.m16n8k16.row.col.f32.bf16.bf16.f32 "
        "{%0,%1,%2,%3}, {%4,%5,%6,%7}, {%8,%9}, {%0,%1,%2,%3};"
        : "+f"(c[0]), "+f"(c[1]), "+f"(c[2]), "+f"(c[3])
        : "r"(a[0]), "r"(a[1]), "r"(a[2]), "r"(a[3]), "r"(b[0]), "r"(b[1]));
}
__device__ __forceinline__ void split2(float v, __nv_bfloat16& h, __nv_bfloat16& l){
    h = __float2bfloat16(v);
    l = __float2bfloat16(v - __bfloat162float(h));
}

// ---------------- scratch ----------------
__device__ __align__(256) __nv_bfloat16 g_pat_h[MALL*PATCHES], g_pat_l[MALL*PATCHES];
__device__ __align__(256) __nv_bfloat16 g_cw_h[NDIM*PATCHES], g_cw_l[NDIM*PATCHES];
__device__ __align__(256) __nv_bfloat16 g_wqkvT_h[NDEPTH*QKVW*NDIM], g_wqkvT_l[NDEPTH*QKVW*NDIM];
__device__ __align__(256) __nv_bfloat16 g_woT_h[NDEPTH*NDIM*NDIM], g_woT_l[NDEPTH*NDIM*NDIM];
__device__ __align__(256) __nv_bfloat16 g_w1T_h[NDEPTH*DMLP*NDIM], g_w1T_l[NDEPTH*DMLP*NDIM];
__device__ __align__(256) __nv_bfloat16 g_w2T_h[NDEPTH*NDIM*DMLP], g_w2T_l[NDEPTH*NDIM*DMLP];
__device__ __align__(256) float         g_x[MALL*NDIM];
__device__ __align__(256) __nv_bfloat16 g_h_h[MALL*NDIM], g_h_l[MALL*NDIM];
__device__ __align__(256) __nv_bfloat16 g_qkv_h[MALL*QKVW], g_qkv_l[MALL*QKVW];
__device__ __align__(256) float         g_scores[NBH*NTOK*NTOK];
__device__ __align__(256) __nv_bfloat16 g_p_h[NBH*NTOK*NTOK], g_p_l[NBH*NTOK*NTOK];
__device__ __align__(256) __nv_bfloat16 g_vt_h[NBH*DHEAD*NTOK], g_vt_l[NBH*DHEAD*NTOK];
__device__ __align__(256) __nv_bfloat16 g_o_h[MALL*NDIM], g_o_l[MALL*NDIM];
__device__ __align__(256) __nv_bfloat16 g_m_h[MALL*DMLP], g_m_l[MALL*DMLP];

// ---------------- prep kernels ----------------
__global__ void im2col_split(const float* __restrict__ vol,
                             __nv_bfloat16* __restrict__ oh, __nv_bfloat16* __restrict__ ol){
    int idx = blockIdx.x * 256 + threadIdx.x;
    int m = idx & 511, tkn = idx >> 9, n = tkn & 511, b = tkn >> 9;
    int k = m & 7, j = (m >> 3) & 7, i = m >> 6;
    int pw = n & 7, ph = (n >> 3) & 7, pd = n >> 6;
    float v = vol[((long)b << 18) + (pd*8+i)*4096 + (ph*8+j)*64 + (pw*8+k)];
    __nv_bfloat16 h, l; split2(v, h, l);
    oh[idx] = h; ol[idx] = l;
}
__global__ void split_plain(const float* __restrict__ in,
                            __nv_bfloat16* __restrict__ oh, __nv_bfloat16* __restrict__ ol, int n){
    int idx = blockIdx.x * 256 + threadIdx.x;
    if (idx >= n) return;
    __nv_bfloat16 h, l; split2(in[idx], h, l);
    oh[idx] = h; ol[idx] = l;
}
// transpose+split: in fp32 [L][R][C] -> out bf16 [L][C][R]
__global__ void wt_split(const float* __restrict__ in,
                         __nv_bfloat16* __restrict__ oh, __nv_bfloat16* __restrict__ ol, int R, int C){
    __shared__ float tf[32][33];
    int z = blockIdx.z;
    const float* ip = in + (long)z * R * C;
    int r0 = blockIdx.y * 32, c0 = blockIdx.x * 32;
    int tx = threadIdx.x, ty = threadIdx.y;
#pragma unroll
    for (int i = 0; i < 4; i++)
        tf[ty + 8*i][tx] = ip[(long)(r0 + ty + 8*i) * C + c0 + tx];
    __syncthreads();
    long ob = (long)z * R * C;
#pragma unroll
    for (int i = 0; i < 4; i++) {
        __nv_bfloat16 h, l; split2(tf[tx][ty + 8*i], h, l);
        long oi = ob + (long)(c0 + ty + 8*i) * R + r0 + tx;
        oh[oi] = h; ol[oi] = l;
    }
}
// transpose V slice of qkv -> vt[z][64][512]
__global__ void vt_split(const __nv_bfloat16* __restrict__ qh, const __nv_bfloat16* __restrict__ ql,
                         __nv_bfloat16* __restrict__ vh, __nv_bfloat16* __restrict__ vl){
    __shared__ __nv_bfloat16 th[32][33], tl[32][33];
    int z = blockIdx.z, b = z / NHEADS, h = z % NHEADS;
    int t0 = blockIdx.x * 32, d0 = blockIdx.y * 32;
    int tx = threadIdx.x, ty = threadIdx.y;
    const long base = (long)b * NTOK * QKVW + 2 * NDIM + h * DHEAD;
#pragma unroll
    for (int i = 0; i < 4; i++) {
        long gi = base + (long)(t0 + ty + 8*i) * QKVW + d0 + tx;
        th[ty + 8*i][tx] = qh[gi]; tl[ty + 8*i][tx] = ql[gi];
    }
    __syncthreads();
    long ob = (long)z * DHEAD * NTOK;
#pragma unroll
    for (int i = 0; i < 4; i++) {
        long oi = ob + (long)(d0 + ty + 8*i) * NTOK + t0 + tx;
        vh[oi] = th[tx][ty + 8*i]; vl[oi] = tl[tx][ty + 8*i];
    }
}

// ---------------- LN (SPLIT=1 bf16 hi/lo out, else fp32) ----------------
template <int SPLIT>
__global__ void ln_kernel(const float* __restrict__ x, const float* __restrict__ w,
                          const float* __restrict__ bb, float* __restrict__ of,
                          __nv_bfloat16* __restrict__ oh, __nv_bfloat16* __restrict__ ol){
    __shared__ float red[8];
    const int row = blockIdx.x, t = threadIdx.x;
    const float* xp = x + (long)row * NDIM;
    float v0 = xp[t], v1 = xp[t+256], v2 = xp[t+512];
    float s = v0 + v1 + v2;
#pragma unroll
    for (int o = 16; o; o >>= 1) s += __shfl_xor_sync(~0u, s, o);
    if ((t & 31) == 0) red[t >> 5] = s;
    __syncthreads();
    if (t < 32) {
        float r = (t < 8) ? red[t] : 0.0f;
#pragma unroll
        for (int o = 4; o; o >>= 1) r += __shfl_xor_sync(~0u, r, o);
        if (t == 0) red[0] = r;
    }
    __syncthreads();
    float mean = red[0] * (1.0f / NDIM);
    __syncthreads();
    float d0 = v0-mean, d1 = v1-mean, d2 = v2-mean;
    float q = d0*d0 + d1*d1 + d2*d2;
#pragma unroll
    for (int o = 16; o; o >>= 1) q += __shfl_xor_sync(~0u, q, o);
    if ((t & 31) == 0) red[t >> 5] = q;
    __syncthreads();
    if (t < 32) {
        float r = (t < 8) ? red[t] : 0.0f;
#pragma unroll
        for (int o = 4; o; o >>= 1) r += __shfl_xor_sync(~0u, r, o);
        if (t == 0) red[0] = r;
    }
    __syncthreads();
    float rs = rsqrtf(red[0] * (1.0f / NDIM) + 1e-5f);
    float y0 = d0*rs*w[t]     + bb[t];
    float y1 = d1*rs*w[t+256] + bb[t+256];
    float y2 = d2*rs*w[t+512] + bb[t+512];
    long o0 = (long)row * NDIM;
    if (SPLIT) {
        __nv_bfloat16 h, l;
        split2(y0,h,l); oh[o0+t]=h;     ol[o0+t]=l;
        split2(y1,h,l); oh[o0+t+256]=h; ol[o0+t+256]=l;
        split2(y2,h,l); oh[o0+t+512]=h; ol[o0+t+512]=l;
    } else {
        of[o0+t]=y0; of[o0+t+256]=y1; of[o0+t+512]=y2;
    }
}

// ---------------- softmax (fp32 scores -> bf16 hi/lo P) ----------------
__global__ void softmax_split(const float* __restrict__ sc,
                              __nv_bfloat16* __restrict__ ph, __nv_bfloat16* __restrict__ pl){
    __shared__ float redm[4], reds[4];
    long rb = (long)blockIdx.x * NTOK;
    const int t = threadIdx.x;
    float4 v = *reinterpret_cast<const float4*>(&sc[rb + t*4]);
    float m = fmaxf(fmaxf(v.x, v.y), fmaxf(v.z, v.w));
#pragma unroll
    for (int o = 16; o; o >>= 1) m = fmaxf(m, __shfl_xor_sync(~0u, m, o));
    if ((t & 31) == 0) redm[t >> 5] = m;
    __syncthreads();
    m = fmaxf(fmaxf(redm[0], redm[1]), fmaxf(redm[2], redm[3]));
    v.x = __expf(v.x-m); v.y = __expf(v.y-m); v.z = __expf(v.z-m); v.w = __expf(v.w-m);
    float s = v.x + v.y + v.z + v.w;
#pragma unroll
    for (int o = 16; o; o >>= 1) s += __shfl_xor_sync(~0u, s, o);
    if ((t & 31) == 0) reds[t >> 5] = s;
    __syncthreads();
    s = reds[0] + reds[1] + reds[2] + reds[3];
    float inv = 1.0f / s;
    __nv_bfloat16 h0,l0,h1,l1,h2,l2,h3,l3;
    split2(v.x*inv,h0,l0); split2(v.y*inv,h1,l1); split2(v.z*inv,h2,l2); split2(v.w*inv,h3,l3);
    long off = rb + t*4;
    __nv_bfloat162 a, b;
    a.x=h0; a.y=h1; b.x=h2; b.y=h3;
    reinterpret_cast<__nv_bfloat162*>(ph+off)[0]=a; reinterpret_cast<__nv_bfloat162*>(ph+off)[1]=b;
    a.x=l0; a.y=l1; b.x=l2; b.y=l3;
    reinterpret_cast<__nv_bfloat162*>(pl+off)[0]=a; reinterpret_cast<__nv_bfloat162*>(pl+off)[1]=b;
}

// ---------------- split-bf16 GEMM via mma.sync ----------------
// C[M,N] = (Ah+Al)[M,K] @ (Bh+Bl)[N,K]^T  (both K-major)
// CTA 128xBN, BK=32, 256 threads = 8 warps (4 M x 2 N), warp tile 32 x BN/2.
// smem rows padded to 80B (conflict-free ldmatrix).
// EPI: 0 fp32*scale | 1 fp32 residual+=acc+bias | 2 tanh(acc+bias)->split
//      3 acc+bias+pos->fp32 | 4 acc->split
template <int BN>
__device__ __forceinline__ void ld_stage(uint32_t sb, int tid,
    const __nv_bfloat16* pAh, const __nv_bfloat16* pAl,
    const __nv_bfloat16* pBh, const __nv_bfloat16* pBl,
    long long lda, long long ldb, int row0, int col0, int k0){
    constexpr int ASZ = 128*80, BSZ2 = BN*80;
#pragma unroll
    for (int i = 0; i < 2; i++) {
        int ch = tid + i*256;           // 0..511
        int r = ch >> 2, c = ch & 3;
        uint32_t so = r*80 + c*16;
        long long go = (long long)(row0 + r) * lda + k0 + c*8;
        CPA16(sb + so, pAh + go);
        CPA16(sb + ASZ + so, pAl + go);
    }
#pragma unroll
    for (int i = 0; i < BN/64; i++) {
        int ch = tid + i*256;           // 0..BN*4-1
        int r = ch >> 2, c = ch & 3;
        uint32_t so = r*80 + c*16;
        long long go = (long long)(col0 + r) * ldb + k0 + c*8;
        CPA16(sb + 2*ASZ + so, pBh + go);
        CPA16(sb + 2*ASZ + BSZ2 + so, pBl + go);
    }
}

template <int BN, int EPI>
__global__ void __launch_bounds__(256, 1) mma_gemm(
    const __nv_bfloat16* __restrict__ Ah, const __nv_bfloat16* __restrict__ Al,
    long long lda, long long aSB, long long aSH,
    const __nv_bfloat16* __restrict__ Bh, const __nv_bfloat16* __restrict__ Bl,
    long long ldb, long long bSB, long long bSH,
    float* __restrict__ Cf, __nv_bfloat16* __restrict__ Oh, __nv_bfloat16* __restrict__ Ol,
    long long ldc, long long cSB, long long cSH,
    const float* __restrict__ bias, const float* __restrict__ pos,
    float scale, int K, int heads)
{
    extern __shared__ __align__(128) char smem_raw[];
    uint32_t sb = smem_u32(smem_raw);
    constexpr int ASZ = 128*80, BSZ2 = BN*80;
    constexpr int BUF = 2*ASZ + 2*BSZ2;
    constexpr int WN = BN/2;     // warp tile N
    constexpr int NP = WN/16;    // ldmatrix n-pairs per warp
    constexpr int NT = WN/8;     // n8 tiles per warp

    const int tid = threadIdx.x, lane = tid & 31, warp = tid >> 5;
    const int warpM = warp & 3, warpN = warp >> 2;
    const int z = blockIdx.z, zb = z / heads, zh = z % heads;
    const __nv_bfloat16* pAh = Ah + zb*aSB + zh*aSH;
    const __nv_bfloat16* pAl = Al + zb*aSB + zh*aSH;
    const __nv_bfloat16* pBh = Bh + zb*bSB + zh*bSH;
    const __nv_bfloat16* pBl = Bl + zb*bSB + zh*bSH;
    const long long cOff = zb*cSB + zh*cSH;
    const int row0 = blockIdx.y * 128, col0 = blockIdx.x * BN;

    float acc[2][NT][4];
#pragma unroll
    for (int a = 0; a < 2; a++)
#pragma unroll
        for (int b = 0; b < NT; b++)
#pragma unroll
            for (int c = 0; c < 4; c++) acc[a][b][c] = 0.0f;

    const int nst = K >> 5;
    ld_stage<BN>(sb, tid, pAh, pAl, pBh, pBl, lda, ldb, row0, col0, 0);
    CP_COMMIT();

    const int L = lane & 7, jj = lane >> 3;
    for (int st = 0; st < nst; st++) {
        if (st + 1 < nst) {
            ld_stage<BN>(sb + ((st+1)&1)*BUF, tid, pAh, pAl, pBh, pBl,
                         lda, ldb, row0, col0, (st+1)*32);
            CP_COMMIT();
            CP_WAIT1();
        } else {
            CP_WAIT0();
        }
        __syncthreads();
        uint32_t base = sb + (st & 1) * BUF;
#pragma unroll
        for (int ks = 0; ks < 2; ks++) {
            uint32_t ah_[2][4], al_[2][4];
#pragma unroll
            for (int mi = 0; mi < 2; mi++) {
                int mrow = warpM*32 + mi*16 + (jj & 1)*8 + L;
                int kcol = ks*16 + (jj >> 1)*8;
                uint32_t ad = base + mrow*80 + kcol*2;
                ldm4(ad, ah_[mi]);
                ldm4(ad + ASZ, al_[mi]);
            }
            uint32_t bh_[NP][4], bl_[NP][4];
#pragma unroll
            for (int np = 0; np < NP; np++) {
                int nrow = warpN*WN + np*16 + (jj >> 1)*8 + L;
                int kcol = ks*16 + (jj & 1)*8;
                uint32_t bd = base + 2*ASZ + nrow*80 + kcol*2;
                ldm4(bd, bh_[np]);
                ldm4(bd + BSZ2, bl_[np]);
            }
#pragma unroll
            for (int mi = 0; mi < 2; mi++)
#pragma unroll
                for (int np = 0; np < NP; np++)
#pragma unroll
                    for (int s = 0; s < 2; s++) {
                        uint32_t bfh[2] = { bh_[np][s*2], bh_[np][s*2+1] };
                        uint32_t bfl[2] = { bl_[np][s*2], bl_[np][s*2+1] };
                        float* c = acc[mi][np*2 + s];
                        mma16816(c, ah_[mi], bfh);
                        mma16816(c, ah_[mi], bfl);
                        mma16816(c, al_[mi], bfh);
                    }
        }
        __syncthreads();
    }

    // epilogue
#pragma unroll
    for (int mi = 0; mi < 2; mi++)
#pragma unroll
        for (int nt = 0; nt < NT; nt++) {
            float* c = acc[mi][nt];
            int col = col0 + warpN*WN + nt*8 + (lane & 3)*2;
#pragma unroll
            for (int hf = 0; hf < 2; hf++) {
                int row = row0 + warpM*32 + mi*16 + (lane >> 2) + hf*8;
                float v0 = c[hf*2 + 0], v1 = c[hf*2 + 1];
                if (EPI == 0) {
                    float2* cp = reinterpret_cast<float2*>(Cf + cOff + (long long)row*ldc + col);
                    *cp = make_float2(v0*scale, v1*scale);
                } else if (EPI == 1) {
                    float2* cp = reinterpret_cast<float2*>(Cf + cOff + (long long)row*ldc + col);
                    float2 old = *cp;
                    *cp = make_float2(old.x + v0 + bias[col], old.y + v1 + bias[col+1]);
                } else if (EPI == 3) {
                    const float2* pp = reinterpret_cast<const float2*>(
                        pos + (long long)(row & (NTOK-1))*ldc + col);
                    float2 pv = *pp;
                    float2* cp = reinterpret_cast<float2*>(Cf + (long long)row*ldc + col);
                    *cp = make_float2(v0 + bias[col] + pv.x, v1 + bias[col+1] + pv.y);
                } else {
                    if (EPI == 2) {
                        v0 = tanhf(v0 + bias[col]);
                        v1 = tanhf(v1 + bias[col+1]);
                    }
                    __nv_bfloat16 h0, l0, h1, l1;
                    split2(v0, h0, l0); split2(v1, h1, l1);
                    long long off = cOff + (long long)row*ldc + col;
                    __nv_bfloat162 hp; hp.x = h0; hp.y = h1;
                    *reinterpret_cast<__nv_bfloat162*>(Oh + off) = hp;
                    __nv_bfloat162 lp; lp.x = l0; lp.y = l1;
                    *reinterpret_cast<__nv_bfloat162*>(Ol + off) = lp;
                }
            }
        }
}

// ---------------- host ----------------
extern "C" void kernel_launch(void* const* d_in, const int* in_sizes, int n_in,
                              void* d_out, int out_size)
{
    const float* volume    = (const float*)d_in[0];
    const float* conv_w    = (const float*)d_in[1];
    const float* conv_b    = (const float*)d_in[2];
    const float* pos_embed = (const float*)d_in[3];
    const float* ln1_w     = (const float*)d_in[4];
    const float* ln1_b     = (const float*)d_in[5];
    const float* w_qkv     = (const float*)d_in[6];
    const float* w_o       = (const float*)d_in[7];
    const float* b_o       = (const float*)d_in[8];
    const float* ln2_w     = (const float*)d_in[9];
    const float* ln2_b     = (const float*)d_in[10];
    const float* w1        = (const float*)d_in[11];
    const float* b1        = (const float*)d_in[12];
    const float* w2        = (const float*)d_in[13];
    const float* b2        = (const float*)d_in[14];
    const float* lnf_w     = (const float*)d_in[15];
    const float* lnf_b     = (const float*)d_in[16];
    float* out = (float*)d_out;

    __nv_bfloat16 *pat_h,*pat_l,*cw_h,*cw_l,*wqT_h,*wqT_l,*woT_h,*woT_l;
    __nv_bfloat16 *w1T_h,*w1T_l,*w2T_h,*w2T_l,*h_h,*h_l,*qkv_h,*qkv_l;
    __nv_bfloat16 *p_h,*p_l,*vt_h,*vt_l,*o_h,*o_l,*m_h,*m_l;
    float *x, *scores;
    cudaGetSymbolAddress((void**)&pat_h, g_pat_h); cudaGetSymbolAddress((void**)&pat_l, g_pat_l);
    cudaGetSymbolAddress((void**)&cw_h, g_cw_h);   cudaGetSymbolAddress((void**)&cw_l, g_cw_l);
    cudaGetSymbolAddress((void**)&wqT_h, g_wqkvT_h); cudaGetSymbolAddress((void**)&wqT_l, g_wqkvT_l);
    cudaGetSymbolAddress((void**)&woT_h, g_woT_h); cudaGetSymbolAddress((void**)&woT_l, g_woT_l);
    cudaGetSymbolAddress((void**)&w1T_h, g_w1T_h); cudaGetSymbolAddress((void**)&w1T_l, g_w1T_l);
    cudaGetSymbolAddress((void**)&w2T_h, g_w2T_h); cudaGetSymbolAddress((void**)&w2T_l, g_w2T_l);
    cudaGetSymbolAddress((void**)&x, g_x);
    cudaGetSymbolAddress((void**)&h_h, g_h_h);     cudaGetSymbolAddress((void**)&h_l, g_h_l);
    cudaGetSymbolAddress((void**)&qkv_h, g_qkv_h); cudaGetSymbolAddress((void**)&qkv_l, g_qkv_l);
    cudaGetSymbolAddress((void**)&scores, g_scores);
    cudaGetSymbolAddress((void**)&p_h, g_p_h);     cudaGetSymbolAddress((void**)&p_l, g_p_l);
    cudaGetSymbolAddress((void**)&vt_h, g_vt_h);   cudaGetSymbolAddress((void**)&vt_l, g_vt_l);
    cudaGetSymbolAddress((void**)&o_h, g_o_h);     cudaGetSymbolAddress((void**)&o_l, g_o_l);
    cudaGetSymbolAddress((void**)&m_h, g_m_h);     cudaGetSymbolAddress((void**)&m_l, g_m_l);

    const int SM128 = 2*(2*128*80 + 2*128*80);   // 81920
    const int SM64  = 2*(2*128*80 + 2*64*80);    // 61440
    cudaFuncSetAttribute(mma_gemm<128,0>, cudaFuncAttributeMaxDynamicSharedMemorySize, SM128);
    cudaFuncSetAttribute(mma_gemm<128,1>, cudaFuncAttributeMaxDynamicSharedMemorySize, SM128);
    cudaFuncSetAttribute(mma_gemm<128,2>, cudaFuncAttributeMaxDynamicSharedMemorySize, SM128);
    cudaFuncSetAttribute(mma_gemm<128,3>, cudaFuncAttributeMaxDynamicSharedMemorySize, SM128);
    cudaFuncSetAttribute(mma_gemm<128,4>, cudaFuncAttributeMaxDynamicSharedMemorySize, SM128);
    cudaFuncSetAttribute(mma_gemm<64,4>,  cudaFuncAttributeMaxDynamicSharedMemorySize, SM64);

    dim3 tb(32, 8);

    im2col_split<<<(MALL*PATCHES)/256, 256>>>(volume, pat_h, pat_l);
    split_plain<<<(NDIM*PATCHES)/256, 256>>>(conv_w, cw_h, cw_l, NDIM*PATCHES);
    wt_split<<<dim3(QKVW/32, NDIM/32, NDEPTH), tb>>>(w_qkv, wqT_h, wqT_l, NDIM, QKVW);
    wt_split<<<dim3(NDIM/32, NDIM/32, NDEPTH), tb>>>(w_o, woT_h, woT_l, NDIM, NDIM);
    wt_split<<<dim3(DMLP/32, NDIM/32, NDEPTH), tb>>>(w1, w1T_h, w1T_l, NDIM, DMLP);
    wt_split<<<dim3(NDIM/32, DMLP/32, NDEPTH), tb>>>(w2, w2T_h, w2T_l, DMLP, NDIM);

    // patch embed: x = patches @ conv_w^T + conv_b + pos
    mma_gemm<128,3><<<dim3(NDIM/128, MALL/128, 1), 256, SM128>>>(
        pat_h, pat_l, PATCHES, 0, 0, cw_h, cw_l, PATCHES, 0, 0,
        x, nullptr, nullptr, NDIM, 0, 0, conv_b, pos_embed, 1.f, PATCHES, 1);

    for (int l = 0; l < NDEPTH; ++l) {
        ln_kernel<1><<<MALL, 256>>>(x, ln1_w + l*NDIM, ln1_b + l*NDIM, nullptr, h_h, h_l);
        mma_gemm<128,4><<<dim3(QKVW/128, MALL/128, 1), 256, SM128>>>(
            h_h, h_l, NDIM, 0, 0, wqT_h + (long)l*QKVW*NDIM, wqT_l + (long)l*QKVW*NDIM, NDIM, 0, 0,
            nullptr, qkv_h, qkv_l, QKVW, 0, 0, nullptr, nullptr, 1.f, NDIM, 1);
        mma_gemm<128,0><<<dim3(NTOK/128, NTOK/128, NBH), 256, SM128>>>(
            qkv_h, qkv_l, QKVW, (long long)NTOK*QKVW, DHEAD,
            qkv_h + NDIM, qkv_l + NDIM, QKVW, (long long)NTOK*QKVW, DHEAD,
            scores, nullptr, nullptr, NTOK, (long long)NHEADS*NTOK*NTOK, (long long)NTOK*NTOK,
            nullptr, nullptr, 0.125f, DHEAD, NHEADS);
        softmax_split<<<NBH*NTOK, 128>>>(scores, p_h, p_l);
        vt_split<<<dim3(NTOK/32, DHEAD/32, NBH), tb>>>(qkv_h, qkv_l, vt_h, vt_l);
        mma_gemm<64,4><<<dim3(1, NTOK/128, NBH), 256, SM64>>>(
            p_h, p_l, NTOK, (long long)NHEADS*NTOK*NTOK, (long long)NTOK*NTOK,
            vt_h, vt_l, NTOK, (long long)NHEADS*DHEAD*NTOK, (long long)DHEAD*NTOK,
            nullptr, o_h, o_l, NDIM, (long long)NTOK*NDIM, DHEAD,
            nullptr, nullptr, 1.f, NTOK, NHEADS);
        mma_gemm<128,1><<<dim3(NDIM/128, MALL/128, 1), 256, SM128>>>(
            o_h, o_l, NDIM, 0, 0, woT_h + (long)l*NDIM*NDIM, woT_l + (long)l*NDIM*NDIM, NDIM, 0, 0,
            x, nullptr, nullptr, NDIM, 0, 0, b_o + l*NDIM, nullptr, 1.f, NDIM, 1);
        ln_kernel<1><<<MALL, 256>>>(x, ln2_w + l*NDIM, ln2_b + l*NDIM, nullptr, h_h, h_l);
        mma_gemm<128,2><<<dim3(DMLP/128, MALL/128, 1), 256, SM128>>>(
            h_h, h_l, NDIM, 0, 0, w1T_h + (long)l*DMLP*NDIM, w1T_l + (long)l*DMLP*NDIM, NDIM, 0, 0,
            nullptr, m_h, m_l, DMLP, 0, 0, b1 + l*DMLP, nullptr, 1.f, NDIM, 1);
        mma_gemm<128,1><<<dim3(NDIM/128, MALL/128, 1), 256, SM128>>>(
            m_h, m_l, DMLP, 0, 0, w2T_h + (long)l*NDIM*DMLP, w2T_l + (long)l*NDIM*DMLP, DMLP, 0, 0,
            x, nullptr, nullptr, NDIM, 0, 0, b2 + l*NDIM, nullptr, 1.f, DMLP, 1);
    }

    ln_kernel<0><<<MALL, 256>>>(x, lnf_w, lnf_b, out, nullptr, nullptr);
}

// round 5
// speedup vs baseline: 2.2680x; 1.3902x over previous
#include <cuda_runtime.h>
#include <cuda_bf16.h>
#include <cstdint>
#include <math.h>

#define NDIM 768
#define NTOK 512
#define BSZ 2
#define MALL 1024
#define NHEADS 12
#define DHEAD 64
#define DMLP 3072
#define NDEPTH 4
#define QKVW 2304
#define PATCHES 512
#define NBH (BSZ*NHEADS)

__device__ __forceinline__ uint32_t smem_u32(const void* p){
    uint32_t a;
    asm("{ .reg .u64 t; cvta.to.shared.u64 t, %1; cvt.u32.u64 %0, t; }" : "=r"(a) : "l"(p));
    return a;
}
#define CPA16(d, s) asm volatile("cp.async.cg.shared.global [%0], [%1], 16;" :: "r"(d), "l"(s))
#define CP_COMMIT() asm volatile("cp.async.commit_group;" ::: "memory")
#define CP_WAIT1()  asm volatile("cp.async.wait_group 1;" ::: "memory")
#define CP_WAIT0()  asm volatile("cp.async.wait_group 0;" ::: "memory")

__device__ __forceinline__ void ldm4(uint32_t addr, uint32_t* r){
    asm volatile("ldmatrix.sync.aligned.m8n8.x4.shared.b16 {%0,%1,%2,%3}, [%4];"
        : "=r"(r[0]), "=r"(r[1]), "=r"(r[2]), "=r"(r[3]) : "r"(addr));
}
__device__ __forceinline__ void mma16816(float* c, const uint32_t* a, const uint32_t* b){
    asm volatile("mma.sync.aligned.m16n8k16.row.col.f32.bf16.bf16.f32 "
        "{%0,%1,%2,%3}, {%4,%5,%6,%7}, {%8,%9}, {%0,%1,%2,%3};"
        : "+f"(c[0]), "+f"(c[1]), "+f"(c[2]), "+f"(c[3])
        : "r"(a[0]), "r"(a[1]), "r"(a[2]), "r"(a[3]), "r"(b[0]), "r"(b[1]));
}
__device__ __forceinline__ void split2(float v, __nv_bfloat16& h, __nv_bfloat16& l){
    h = __float2bfloat16(v);
    l = __float2bfloat16(v - __bfloat162float(h));
}

// ---------------- scratch ----------------
__device__ __align__(256) __nv_bfloat16 g_pat_h[MALL*PATCHES], g_pat_l[MALL*PATCHES];
__device__ __align__(256) __nv_bfloat16 g_cw_h[NDIM*PATCHES], g_cw_l[NDIM*PATCHES];
__device__ __align__(256) __nv_bfloat16 g_wqkvT_h[NDEPTH*QKVW*NDIM], g_wqkvT_l[NDEPTH*QKVW*NDIM];
__device__ __align__(256) __nv_bfloat16 g_woT_h[NDEPTH*NDIM*NDIM], g_woT_l[NDEPTH*NDIM*NDIM];
__device__ __align__(256) __nv_bfloat16 g_w1T_h[NDEPTH*DMLP*NDIM], g_w1T_l[NDEPTH*DMLP*NDIM];
__device__ __align__(256) __nv_bfloat16 g_w2T_h[NDEPTH*NDIM*DMLP], g_w2T_l[NDEPTH*NDIM*DMLP];
__device__ __align__(256) float         g_x[MALL*NDIM];
__device__ __align__(256) __nv_bfloat16 g_h_h[MALL*NDIM], g_h_l[MALL*NDIM];
__device__ __align__(256) __nv_bfloat16 g_qkv_h[MALL*QKVW], g_qkv_l[MALL*QKVW];
__device__ __align__(256) float         g_scores[NBH*NTOK*NTOK];
__device__ __align__(256) __nv_bfloat16 g_p_h[NBH*NTOK*NTOK], g_p_l[NBH*NTOK*NTOK];
__device__ __align__(256) __nv_bfloat16 g_vt_h[NBH*DHEAD*NTOK], g_vt_l[NBH*DHEAD*NTOK];
__device__ __align__(256) __nv_bfloat16 g_o_h[MALL*NDIM], g_o_l[MALL*NDIM];
__device__ __align__(256) __nv_bfloat16 g_m_h[MALL*DMLP], g_m_l[MALL*DMLP];

// ---------------- prep kernels ----------------
__global__ void im2col_split(const float* __restrict__ vol,
                             __nv_bfloat16* __restrict__ oh, __nv_bfloat16* __restrict__ ol){
    int idx = blockIdx.x * 256 + threadIdx.x;
    int m = idx & 511, tkn = idx >> 9, n = tkn & 511, b = tkn >> 9;
    int k = m & 7, j = (m >> 3) & 7, i = m >> 6;
    int pw = n & 7, ph = (n >> 3) & 7, pd = n >> 6;
    float v = vol[((long)b << 18) + (pd*8+i)*4096 + (ph*8+j)*64 + (pw*8+k)];
    __nv_bfloat16 h, l; split2(v, h, l);
    oh[idx] = h; ol[idx] = l;
}
__global__ void split_plain(const float* __restrict__ in,
                            __nv_bfloat16* __restrict__ oh, __nv_bfloat16* __restrict__ ol, int n){
    int idx = blockIdx.x * 256 + threadIdx.x;
    if (idx >= n) return;
    __nv_bfloat16 h, l; split2(in[idx], h, l);
    oh[idx] = h; ol[idx] = l;
}
// transpose+split: in fp32 [L][R][C] -> out bf16 [L][C][R]
__global__ void wt_split(const float* __restrict__ in,
                         __nv_bfloat16* __restrict__ oh, __nv_bfloat16* __restrict__ ol, int R, int C){
    __shared__ float tf[32][33];
    int z = blockIdx.z;
    const float* ip = in + (long)z * R * C;
    int r0 = blockIdx.y * 32, c0 = blockIdx.x * 32;
    int tx = threadIdx.x, ty = threadIdx.y;
#pragma unroll
    for (int i = 0; i < 4; i++)
        tf[ty + 8*i][tx] = ip[(long)(r0 + ty + 8*i) * C + c0 + tx];
    __syncthreads();
    long ob = (long)z * R * C;
#pragma unroll
    for (int i = 0; i < 4; i++) {
        __nv_bfloat16 h, l; split2(tf[tx][ty + 8*i], h, l);
        long oi = ob + (long)(c0 + ty + 8*i) * R + r0 + tx;
        oh[oi] = h; ol[oi] = l;
    }
}
// transpose V slice of qkv -> vt[z][64][512]
__global__ void vt_split(const __nv_bfloat16* __restrict__ qh, const __nv_bfloat16* __restrict__ ql,
                         __nv_bfloat16* __restrict__ vh, __nv_bfloat16* __restrict__ vl){
    __shared__ __nv_bfloat16 th[32][33], tl[32][33];
    int z = blockIdx.z, b = z / NHEADS, h = z % NHEADS;
    int t0 = blockIdx.x * 32, d0 = blockIdx.y * 32;
    int tx = threadIdx.x, ty = threadIdx.y;
    const long base = (long)b * NTOK * QKVW + 2 * NDIM + h * DHEAD;
#pragma unroll
    for (int i = 0; i < 4; i++) {
        long gi = base + (long)(t0 + ty + 8*i) * QKVW + d0 + tx;
        th[ty + 8*i][tx] = qh[gi]; tl[ty + 8*i][tx] = ql[gi];
    }
    __syncthreads();
    long ob = (long)z * DHEAD * NTOK;
#pragma unroll
    for (int i = 0; i < 4; i++) {
        long oi = ob + (long)(d0 + ty + 8*i) * NTOK + t0 + tx;
        vh[oi] = th[tx][ty + 8*i]; vl[oi] = tl[tx][ty + 8*i];
    }
}

// ---------------- LN ----------------
template <int SPLIT>
__global__ void ln_kernel(const float* __restrict__ x, const float* __restrict__ w,
                          const float* __restrict__ bb, float* __restrict__ of,
                          __nv_bfloat16* __restrict__ oh, __nv_bfloat16* __restrict__ ol){
    __shared__ float red[8];
    const int row = blockIdx.x, t = threadIdx.x;
    const float* xp = x + (long)row * NDIM;
    float v0 = xp[t], v1 = xp[t+256], v2 = xp[t+512];
    float s = v0 + v1 + v2;
#pragma unroll
    for (int o = 16; o; o >>= 1) s += __shfl_xor_sync(~0u, s, o);
    if ((t & 31) == 0) red[t >> 5] = s;
    __syncthreads();
    if (t < 32) {
        float r = (t < 8) ? red[t] : 0.0f;
#pragma unroll
        for (int o = 4; o; o >>= 1) r += __shfl_xor_sync(~0u, r, o);
        if (t == 0) red[0] = r;
    }
    __syncthreads();
    float mean = red[0] * (1.0f / NDIM);
    __syncthreads();
    float d0 = v0-mean, d1 = v1-mean, d2 = v2-mean;
    float q = d0*d0 + d1*d1 + d2*d2;
#pragma unroll
    for (int o = 16; o; o >>= 1) q += __shfl_xor_sync(~0u, q, o);
    if ((t & 31) == 0) red[t >> 5] = q;
    __syncthreads();
    if (t < 32) {
        float r = (t < 8) ? red[t] : 0.0f;
#pragma unroll
        for (int o = 4; o; o >>= 1) r += __shfl_xor_sync(~0u, r, o);
        if (t == 0) red[0] = r;
    }
    __syncthreads();
    float rs = rsqrtf(red[0] * (1.0f / NDIM) + 1e-5f);
    float y0 = d0*rs*w[t]     + bb[t];
    float y1 = d1*rs*w[t+256] + bb[t+256];
    float y2 = d2*rs*w[t+512] + bb[t+512];
    long o0 = (long)row * NDIM;
    if (SPLIT) {
        __nv_bfloat16 h, l;
        split2(y0,h,l); oh[o0+t]=h;     ol[o0+t]=l;
        split2(y1,h,l); oh[o0+t+256]=h; ol[o0+t+256]=l;
        split2(y2,h,l); oh[o0+t+512]=h; ol[o0+t+512]=l;
    } else {
        of[o0+t]=y0; of[o0+t+256]=y1; of[o0+t+512]=y2;
    }
}

// ---------------- softmax ----------------
__global__ void softmax_split(const float* __restrict__ sc,
                              __nv_bfloat16* __restrict__ ph, __nv_bfloat16* __restrict__ pl){
    __shared__ float redm[4], reds[4];
    long rb = (long)blockIdx.x * NTOK;
    const int t = threadIdx.x;
    float4 v = *reinterpret_cast<const float4*>(&sc[rb + t*4]);
    float m = fmaxf(fmaxf(v.x, v.y), fmaxf(v.z, v.w));
#pragma unroll
    for (int o = 16; o; o >>= 1) m = fmaxf(m, __shfl_xor_sync(~0u, m, o));
    if ((t & 31) == 0) redm[t >> 5] = m;
    __syncthreads();
    m = fmaxf(fmaxf(redm[0], redm[1]), fmaxf(redm[2], redm[3]));
    v.x = __expf(v.x-m); v.y = __expf(v.y-m); v.z = __expf(v.z-m); v.w = __expf(v.w-m);
    float s = v.x + v.y + v.z + v.w;
#pragma unroll
    for (int o = 16; o; o >>= 1) s += __shfl_xor_sync(~0u, s, o);
    if ((t & 31) == 0) reds[t >> 5] = s;
    __syncthreads();
    s = reds[0] + reds[1] + reds[2] + reds[3];
    float inv = 1.0f / s;
    __nv_bfloat16 h0,l0,h1,l1,h2,l2,h3,l3;
    split2(v.x*inv,h0,l0); split2(v.y*inv,h1,l1); split2(v.z*inv,h2,l2); split2(v.w*inv,h3,l3);
    long off = rb + t*4;
    __nv_bfloat162 a, b;
    a.x=h0; a.y=h1; b.x=h2; b.y=h3;
    reinterpret_cast<__nv_bfloat162*>(ph+off)[0]=a; reinterpret_cast<__nv_bfloat162*>(ph+off)[1]=b;
    a.x=l0; a.y=l1; b.x=l2; b.y=l3;
    reinterpret_cast<__nv_bfloat162*>(pl+off)[0]=a; reinterpret_cast<__nv_bfloat162*>(pl+off)[1]=b;
}

// ---------------- split-bf16 GEMM via mma.sync ----------------
// C[M,N] = (Ah+Al)[M,K] @ (Bh+Bl)[N,K]^T, 3-stage cp.async ring, 1 sync/stage.
// 256 thr = 8 warps laid out (BM/32) x (8/(BM/32)); warp tile 32 x (BN/(8/(BM/32))).
template <int BM, int BN>
__device__ __forceinline__ void ld_stage(uint32_t sb, int tid,
    const __nv_bfloat16* pAh, const __nv_bfloat16* pAl,
    const __nv_bfloat16* pBh, const __nv_bfloat16* pBl,
    long long lda, long long ldb, int row0, int col0, int k0){
    constexpr int ASZ = BM*80, BSZ2 = BN*80;
#pragma unroll
    for (int i = 0; i < BM/64; i++) {
        int ch = tid + i*256;
        int r = ch >> 2, c = ch & 3;
        uint32_t so = r*80 + c*16;
        long long go = (long long)(row0 + r) * lda + k0 + c*8;
        CPA16(sb + so, pAh + go);
        CPA16(sb + ASZ + so, pAl + go);
    }
#pragma unroll
    for (int i = 0; i < BN/64; i++) {
        int ch = tid + i*256;
        int r = ch >> 2, c = ch & 3;
        uint32_t so = r*80 + c*16;
        long long go = (long long)(col0 + r) * ldb + k0 + c*8;
        CPA16(sb + 2*ASZ + so, pBh + go);
        CPA16(sb + 2*ASZ + BSZ2 + so, pBl + go);
    }
}

template <int BM, int BN, int EPI>
__global__ void __launch_bounds__(256, 1) mma_gemm(
    const __nv_bfloat16* __restrict__ Ah, const __nv_bfloat16* __restrict__ Al,
    long long lda, long long aSB, long long aSH,
    const __nv_bfloat16* __restrict__ Bh, const __nv_bfloat16* __restrict__ Bl,
    long long ldb, long long bSB, long long bSH,
    float* __restrict__ Cf, __nv_bfloat16* __restrict__ Oh, __nv_bfloat16* __restrict__ Ol,
    long long ldc, long long cSB, long long cSH,
    const float* __restrict__ bias, const float* __restrict__ pos,
    float scale, int K, int heads)
{
    extern __shared__ __align__(128) char smem_raw[];
    uint32_t sb = smem_u32(smem_raw);
    constexpr int ASZ = BM*80, BSZ2 = BN*80;
    constexpr int BUF = 2*ASZ + 2*BSZ2;
    constexpr int MW = BM/32;        // M warps
    constexpr int NW = 8/MW;         // N warps
    constexpr int WN = BN/NW;        // warp tile N
    constexpr int NP = WN/16;
    constexpr int NT = WN/8;

    const int tid = threadIdx.x, lane = tid & 31, warp = tid >> 5;
    const int warpM = warp % MW, warpN = warp / MW;
    const int z = blockIdx.z, zb = z / heads, zh = z % heads;
    const __nv_bfloat16* pAh = Ah + zb*aSB + zh*aSH;
    const __nv_bfloat16* pAl = Al + zb*aSB + zh*aSH;
    const __nv_bfloat16* pBh = Bh + zb*bSB + zh*bSH;
    const __nv_bfloat16* pBl = Bl + zb*bSB + zh*bSH;
    const long long cOff = zb*cSB + zh*cSH;
    const int row0 = blockIdx.y * BM, col0 = blockIdx.x * BN;

    float acc[2][NT][4];
#pragma unroll
    for (int a = 0; a < 2; a++)
#pragma unroll
        for (int b = 0; b < NT; b++)
#pragma unroll
            for (int c = 0; c < 4; c++) acc[a][b][c] = 0.0f;

    const int nst = K >> 5;
    ld_stage<BM,BN>(sb, tid, pAh, pAl, pBh, pBl, lda, ldb, row0, col0, 0);
    CP_COMMIT();
    if (nst > 1) {
        ld_stage<BM,BN>(sb + BUF, tid, pAh, pAl, pBh, pBl, lda, ldb, row0, col0, 32);
        CP_COMMIT();
    }

    const int L = lane & 7, jj = lane >> 3;
    for (int st = 0; st < nst; st++) {
        if (st < nst - 1) CP_WAIT1(); else CP_WAIT0();
        __syncthreads();
        if (st + 2 < nst) {
            ld_stage<BM,BN>(sb + ((st+2)%3)*BUF, tid, pAh, pAl, pBh, pBl,
                            lda, ldb, row0, col0, (st+2)*32);
            CP_COMMIT();
        }
        uint32_t base = sb + (st % 3) * BUF;
#pragma unroll
        for (int ks = 0; ks < 2; ks++) {
            uint32_t ah_[2][4], al_[2][4];
#pragma unroll
            for (int mi = 0; mi < 2; mi++) {
                int mrow = warpM*32 + mi*16 + (jj & 1)*8 + L;
                int kcol = ks*16 + (jj >> 1)*8;
                uint32_t ad = base + mrow*80 + kcol*2;
                ldm4(ad, ah_[mi]);
                ldm4(ad + ASZ, al_[mi]);
            }
            uint32_t bh_[NP][4], bl_[NP][4];
#pragma unroll
            for (int np = 0; np < NP; np++) {
                int nrow = warpN*WN + np*16 + (jj >> 1)*8 + L;
                int kcol = ks*16 + (jj & 1)*8;
                uint32_t bd = base + 2*ASZ + nrow*80 + kcol*2;
                ldm4(bd, bh_[np]);
                ldm4(bd + BSZ2, bl_[np]);
            }
#pragma unroll
            for (int mi = 0; mi < 2; mi++)
#pragma unroll
                for (int np = 0; np < NP; np++)
#pragma unroll
                    for (int s = 0; s < 2; s++) {
                        uint32_t bfh[2] = { bh_[np][s*2], bh_[np][s*2+1] };
                        uint32_t bfl[2] = { bl_[np][s*2], bl_[np][s*2+1] };
                        float* c = acc[mi][np*2 + s];
                        mma16816(c, ah_[mi], bfh);
                        mma16816(c, ah_[mi], bfl);
                        mma16816(c, al_[mi], bfh);
                    }
        }
    }

    // epilogue
#pragma unroll
    for (int mi = 0; mi < 2; mi++)
#pragma unroll
        for (int nt = 0; nt < NT; nt++) {
            float* c = acc[mi][nt];
            int col = col0 + warpN*WN + nt*8 + (lane & 3)*2;
#pragma unroll
            for (int hf = 0; hf < 2; hf++) {
                int row = row0 + warpM*32 + mi*16 + (lane >> 2) + hf*8;
                float v0 = c[hf*2 + 0], v1 = c[hf*2 + 1];
                if (EPI == 0) {
                    float2* cp = reinterpret_cast<float2*>(Cf + cOff + (long long)row*ldc + col);
                    *cp = make_float2(v0*scale, v1*scale);
                } else if (EPI == 1) {
                    float2* cp = reinterpret_cast<float2*>(Cf + cOff + (long long)row*ldc + col);
                    float2 old = *cp;
                    *cp = make_float2(old.x + v0 + bias[col], old.y + v1 + bias[col+1]);
                } else if (EPI == 3) {
                    const float2* pp = reinterpret_cast<const float2*>(
                        pos + (long long)(row & (NTOK-1))*ldc + col);
                    float2 pv = *pp;
                    float2* cp = reinterpret_cast<float2*>(Cf + (long long)row*ldc + col);
                    *cp = make_float2(v0 + bias[col] + pv.x, v1 + bias[col+1] + pv.y);
                } else {
                    if (EPI == 2) {
                        v0 = tanhf(v0 + bias[col]);
                        v1 = tanhf(v1 + bias[col+1]);
                    }
                    __nv_bfloat16 h0, l0, h1, l1;
                    split2(v0, h0, l0); split2(v1, h1, l1);
                    long long off = cOff + (long long)row*ldc + col;
                    __nv_bfloat162 hp; hp.x = h0; hp.y = h1;
                    *reinterpret_cast<__nv_bfloat162*>(Oh + off) = hp;
                    __nv_bfloat162 lp; lp.x = l0; lp.y = l1;
                    *reinterpret_cast<__nv_bfloat162*>(Ol + off) = lp;
                }
            }
        }
}

// ---------------- host ----------------
extern "C" void kernel_launch(void* const* d_in, const int* in_sizes, int n_in,
                              void* d_out, int out_size)
{
    const float* volume    = (const float*)d_in[0];
    const float* conv_w    = (const float*)d_in[1];
    const float* conv_b    = (const float*)d_in[2];
    const float* pos_embed = (const float*)d_in[3];
    const float* ln1_w     = (const float*)d_in[4];
    const float* ln1_b     = (const float*)d_in[5];
    const float* w_qkv     = (const float*)d_in[6];
    const float* w_o       = (const float*)d_in[7];
    const float* b_o       = (const float*)d_in[8];
    const float* ln2_w     = (const float*)d_in[9];
    const float* ln2_b     = (const float*)d_in[10];
    const float* w1        = (const float*)d_in[11];
    const float* b1        = (const float*)d_in[12];
    const float* w2        = (const float*)d_in[13];
    const float* b2        = (const float*)d_in[14];
    const float* lnf_w     = (const float*)d_in[15];
    const float* lnf_b     = (const float*)d_in[16];
    float* out = (float*)d_out;

    __nv_bfloat16 *pat_h,*pat_l,*cw_h,*cw_l,*wqT_h,*wqT_l,*woT_h,*woT_l;
    __nv_bfloat16 *w1T_h,*w1T_l,*w2T_h,*w2T_l,*h_h,*h_l,*qkv_h,*qkv_l;
    __nv_bfloat16 *p_h,*p_l,*vt_h,*vt_l,*o_h,*o_l,*m_h,*m_l;
    float *x, *scores;
    cudaGetSymbolAddress((void**)&pat_h, g_pat_h); cudaGetSymbolAddress((void**)&pat_l, g_pat_l);
    cudaGetSymbolAddress((void**)&cw_h, g_cw_h);   cudaGetSymbolAddress((void**)&cw_l, g_cw_l);
    cudaGetSymbolAddress((void**)&wqT_h, g_wqkvT_h); cudaGetSymbolAddress((void**)&wqT_l, g_wqkvT_l);
    cudaGetSymbolAddress((void**)&woT_h, g_woT_h); cudaGetSymbolAddress((void**)&woT_l, g_woT_l);
    cudaGetSymbolAddress((void**)&w1T_h, g_w1T_h); cudaGetSymbolAddress((void**)&w1T_l, g_w1T_l);
    cudaGetSymbolAddress((void**)&w2T_h, g_w2T_h); cudaGetSymbolAddress((void**)&w2T_l, g_w2T_l);
    cudaGetSymbolAddress((void**)&x, g_x);
    cudaGetSymbolAddress((void**)&h_h, g_h_h);     cudaGetSymbolAddress((void**)&h_l, g_h_l);
    cudaGetSymbolAddress((void**)&qkv_h, g_qkv_h); cudaGetSymbolAddress((void**)&qkv_l, g_qkv_l);
    cudaGetSymbolAddress((void**)&scores, g_scores);
    cudaGetSymbolAddress((void**)&p_h, g_p_h);     cudaGetSymbolAddress((void**)&p_l, g_p_l);
    cudaGetSymbolAddress((void**)&vt_h, g_vt_h);   cudaGetSymbolAddress((void**)&vt_l, g_vt_l);
    cudaGetSymbolAddress((void**)&o_h, g_o_h);     cudaGetSymbolAddress((void**)&o_l, g_o_l);
    cudaGetSymbolAddress((void**)&m_h, g_m_h);     cudaGetSymbolAddress((void**)&m_l, g_m_l);

    const int S_128_128 = 3*(2*128*80 + 2*128*80);  // 122880
    const int S_128_192 = 3*(2*128*80 + 2*192*80);  // 153600
    const int S_128_64  = 3*(2*128*80 + 2*64*80);   // 92160
    const int S_64_64   = 3*(2*64*80  + 2*64*80);   // 61440
    cudaFuncSetAttribute(mma_gemm<128,128,0>, cudaFuncAttributeMaxDynamicSharedMemorySize, S_128_128);
    cudaFuncSetAttribute(mma_gemm<128,128,4>, cudaFuncAttributeMaxDynamicSharedMemorySize, S_128_128);
    cudaFuncSetAttribute(mma_gemm<128,192,2>, cudaFuncAttributeMaxDynamicSharedMemorySize, S_128_192);
    cudaFuncSetAttribute(mma_gemm<128,64,4>,  cudaFuncAttributeMaxDynamicSharedMemorySize, S_128_64);
    cudaFuncSetAttribute(mma_gemm<64,64,1>,   cudaFuncAttributeMaxDynamicSharedMemorySize, S_64_64);
    cudaFuncSetAttribute(mma_gemm<64,64,3>,   cudaFuncAttributeMaxDynamicSharedMemorySize, S_64_64);

    dim3 tb(32, 8);

    im2col_split<<<(MALL*PATCHES)/256, 256>>>(volume, pat_h, pat_l);
    split_plain<<<(NDIM*PATCHES)/256, 256>>>(conv_w, cw_h, cw_l, NDIM*PATCHES);
    wt_split<<<dim3(QKVW/32, NDIM/32, NDEPTH), tb>>>(w_qkv, wqT_h, wqT_l, NDIM, QKVW);
    wt_split<<<dim3(NDIM/32, NDIM/32, NDEPTH), tb>>>(w_o, woT_h, woT_l, NDIM, NDIM);
    wt_split<<<dim3(DMLP/32, NDIM/32, NDEPTH), tb>>>(w1, w1T_h, w1T_l, NDIM, DMLP);
    wt_split<<<dim3(NDIM/32, DMLP/32, NDEPTH), tb>>>(w2, w2T_h, w2T_l, DMLP, NDIM);

    // patch embed: x = patches @ conv_w^T + conv_b + pos  (192 CTAs)
    mma_gemm<64,64,3><<<dim3(NDIM/64, MALL/64, 1), 256, S_64_64>>>(
        pat_h, pat_l, PATCHES, 0, 0, cw_h, cw_l, PATCHES, 0, 0,
        x, nullptr, nullptr, NDIM, 0, 0, conv_b, pos_embed, 1.f, PATCHES, 1);

    for (int l = 0; l < NDEPTH; ++l) {
        ln_kernel<1><<<MALL, 256>>>(x, ln1_w + l*NDIM, ln1_b + l*NDIM, nullptr, h_h, h_l);
        mma_gemm<128,128,4><<<dim3(QKVW/128, MALL/128, 1), 256, S_128_128>>>(
            h_h, h_l, NDIM, 0, 0, wqT_h + (long)l*QKVW*NDIM, wqT_l + (long)l*QKVW*NDIM, NDIM, 0, 0,
            nullptr, qkv_h, qkv_l, QKVW, 0, 0, nullptr, nullptr, 1.f, NDIM, 1);
        mma_gemm<128,128,0><<<dim3(NTOK/128, NTOK/128, NBH), 256, S_128_128>>>(
            qkv_h, qkv_l, QKVW, (long long)NTOK*QKVW, DHEAD,
            qkv_h + NDIM, qkv_l + NDIM, QKVW, (long long)NTOK*QKVW, DHEAD,
            scores, nullptr, nullptr, NTOK, (long long)NHEADS*NTOK*NTOK, (long long)NTOK*NTOK,
            nullptr, nullptr, 0.125f, DHEAD, NHEADS);
        softmax_split<<<NBH*NTOK, 128>>>(scores, p_h, p_l);
        vt_split<<<dim3(NTOK/32, DHEAD/32, NBH), tb>>>(qkv_h, qkv_l, vt_h, vt_l);
        mma_gemm<128,64,4><<<dim3(1, NTOK/128, NBH), 256, S_128_64>>>(
            p_h, p_l, NTOK, (long long)NHEADS*NTOK*NTOK, (long long)NTOK*NTOK,
            vt_h, vt_l, NTOK, (long long)NHEADS*DHEAD*NTOK, (long long)DHEAD*NTOK,
            nullptr, o_h, o_l, NDIM, (long long)NTOK*NDIM, DHEAD,
            nullptr, nullptr, 1.f, NTOK, NHEADS);
        mma_gemm<64,64,1><<<dim3(NDIM/64, MALL/64, 1), 256, S_64_64>>>(
            o_h, o_l, NDIM, 0, 0, woT_h + (long)l*NDIM*NDIM, woT_l + (long)l*NDIM*NDIM, NDIM, 0, 0,
            x, nullptr, nullptr, NDIM, 0, 0, b_o + l*NDIM, nullptr, 1.f, NDIM, 1);
        ln_kernel<1><<<MALL, 256>>>(x, ln2_w + l*NDIM, ln2_b + l*NDIM, nullptr, h_h, h_l);
        mma_gemm<128,192,2><<<dim3(DMLP/192, MALL/128, 1), 256, S_128_192>>>(
            h_h, h_l, NDIM, 0, 0, w1T_h + (long)l*DMLP*NDIM, w1T_l + (long)l*DMLP*NDIM, NDIM, 0, 0,
            nullptr, m_h, m_l, DMLP, 0, 0, b1 + l*DMLP, nullptr, 1.f, NDIM, 1);
        mma_gemm<64,64,1><<<dim3(NDIM/64, MALL/64, 1), 256, S_64_64>>>(
            m_h, m_l, DMLP, 0, 0, w2T_h + (long)l*NDIM*DMLP, w2T_l + (long)l*NDIM*DMLP, DMLP, 0, 0,
            x, nullptr, nullptr, NDIM, 0, 0, b2 + l*NDIM, nullptr, 1.f, DMLP, 1);
    }

    ln_kernel<0><<<MALL, 256>>>(x, lnf_w, lnf_b, out, nullptr, nullptr);
}